// round 1
// baseline (speedup 1.0000x reference)
#include <cuda_runtime.h>
#include <cstdint>

// SpatialPool: fm [B=16, C=512, H=38, W=38] f32 (NCHW)
//   -> out [B, H*W, 9*C] f32 where out[b, h*W+w, (di*3+dj)*C + c]
//      = fm[b, c, clamp(h+di-1), clamp(w+dj-1)]  (replicate pad)
//
// Strategy: fused smem transpose + gather.
//   CTA = (w-half, y, b). Loads 3 rows x 21 cols x 512 C into smem
//   (clamped at load), then writes 19*9 fully-coalesced 2KB channel
//   chunks with float4 stores. Output traffic (426 MB) is the roofline.

namespace {
constexpr int HH  = 38;
constexpr int C   = 512;
constexpr int NB  = 9;
constexpr int WT  = 19;        // w positions per CTA (38 = 2*19)
constexpr int LW  = WT + 2;    // local cols incl. halo = 21
constexpr int CP  = C + 4;     // padded channel stride (516): 16B-aligned rows,
                               // breaks 32-way bank conflicts on transpose STS
constexpr int SMEM_BYTES = 3 * LW * CP * 4;   // 130,032 B
constexpr int THREADS = 512;
}

__global__ __launch_bounds__(THREADS, 1)
void spatialpool_kernel(const float* __restrict__ fm, float* __restrict__ out) {
    extern __shared__ float sm[];

    const int w0 = blockIdx.x * WT;   // 0 or 19
    const int y  = blockIdx.y;        // 0..37
    const int b  = blockIdx.z;        // 0..15

    const float* __restrict__ fb = fm + (size_t)b * C * HH * HH;

    // ---- Load phase: NCHW -> smem[pos][c], clamp folded in here ----
    // smem row r in {0,1,2} holds input row clamp(y-1+r); local col l in
    // [0,21) holds input col clamp(w0-1+l). Global reads are contiguous
    // runs of 21 floats (coalesced-ish; input is small and L2-resident).
    for (int idx = threadIdx.x; idx < 3 * C * LW; idx += THREADS) {
        int r   = idx / (C * LW);
        int rem = idx - r * (C * LW);
        int c   = rem / LW;
        int l   = rem - c * LW;
        int yl  = min(max(y - 1 + r, 0), HH - 1);
        int xg  = min(max(w0 - 1 + l, 0), HH - 1);
        sm[(r * LW + l) * CP + c] = fb[(size_t)c * (HH * HH) + yl * HH + xg];
    }
    __syncthreads();

    // ---- Write phase: fully coalesced float4 stores, no clamps ----
    // For output (w, n=(di,dj)): value[c] = sm[(di*LW + (w-w0) + dj)*CP + c].
    // Chunk = 512 floats = 128 float4. 19*9 = 171 chunks per CTA.
    float4* __restrict__ out4 = (float4*)out;
    const size_t rowbase =
        ((size_t)b * (HH * HH) + (size_t)y * HH + w0) * (size_t)(NB * C / 4);

    for (int it = threadIdx.x; it < WT * NB * 128; it += THREADS) {
        int c4 = it & 127;        // float4 index within chunk
        int t  = it >> 7;         // chunk id = wl*9 + n
        int n  = t % NB;
        int wl = t / NB;
        int di = n / 3;
        int dj = n - di * 3;
        int pos = di * LW + wl + dj;

        float4 v = *(const float4*)&sm[pos * CP + c4 * 4];
        out4[rowbase + (size_t)wl * (NB * C / 4) + n * (C / 4) + c4] = v;
    }
}

extern "C" void kernel_launch(void* const* d_in, const int* in_sizes, int n_in,
                              void* d_out, int out_size) {
    const float* fm = (const float*)d_in[0];
    float* out = (float*)d_out;
    (void)in_sizes; (void)n_in; (void)out_size;

    // Opt into >48KB dynamic smem (idempotent; executes immediately even
    // under graph capture — it is not a stream operation).
    cudaFuncSetAttribute(spatialpool_kernel,
                         cudaFuncAttributeMaxDynamicSharedMemorySize,
                         SMEM_BYTES);

    dim3 grid(HH / WT, HH, 16);   // (2, 38, 16) = 1216 CTAs
    spatialpool_kernel<<<grid, THREADS, SMEM_BYTES>>>(fm, out);
}

// round 2
// speedup vs baseline: 1.4318x; 1.4318x over previous
#include <cuda_runtime.h>
#include <cstdint>

// SpatialPool: fm [B=16, C=512, H=38, W=38] f32 (NCHW)
//   -> out [B, H*W, 9*C] f32, out[b, h*W+w, (di*3+dj)*C + c]
//      = fm[b, c, clamp(h+di-1), clamp(w+dj-1)]  (replicate pad)
//
// R2: channel-split (128 C per CTA) for 3 CTAs/SM occupancy, conflict-free
// smem layouts, warp-per-chunk write loop (1 LDS.128 + 1 STG.128 per lane).

namespace {
constexpr int HH   = 38;
constexpr int C    = 512;
constexpr int CSUB = 128;       // channels per CTA
constexpr int NCG  = C / CSUB;  // 4 channel groups
constexpr int NB   = 9;
constexpr int WT   = 19;        // w positions per CTA (38 = 2*19)
constexpr int LW   = WT + 2;    // 21 local cols incl. halo
constexpr int CP   = CSUB;      // smem channel stride (128) — conflict-free
constexpr int THREADS = 512;
}

__global__ __launch_bounds__(THREADS, 3)
void spatialpool_kernel(const float* __restrict__ fm, float* __restrict__ out) {
    __shared__ float sm[3 * LW * CP];   // 32,256 B

    const int wh = blockIdx.x & 1;          // w half
    const int cg = blockIdx.x >> 1;         // channel group 0..3
    const int w0 = wh * WT;
    const int y  = blockIdx.y;
    const int b  = blockIdx.z;

    const float* __restrict__ fb =
        fm + ((size_t)b * C + (size_t)cg * CSUB) * (HH * HH);

    // ---- Load: one thread per (r, c) copies its 21-col run (clamped). ----
    // Consecutive threads -> consecutive c -> smem bank stride 1 (no conflicts).
    const int t = threadIdx.x;
    if (t < 3 * CSUB) {
        const int r = t >> 7;        // 0..2
        const int c = t & 127;
        const int yl = min(max(y - 1 + r, 0), HH - 1);
        const float* __restrict__ src = fb + (size_t)c * (HH * HH) + yl * HH;
        float* __restrict__ dst = &sm[(r * LW) * CP + c];
        #pragma unroll
        for (int l = 0; l < LW; ++l) {
            int xg = min(max(w0 - 1 + l, 0), HH - 1);
            dst[l * CP] = src[xg];
        }
    }
    __syncthreads();

    // ---- Write: warp-per-chunk. Chunk = (wl, n) = 128 floats = 32 float4.
    // Each lane: one LDS.128 + one STG.128. Fully coalesced 512B stores. ----
    const int wid  = threadIdx.x >> 5;
    const int lane = threadIdx.x & 31;
    float4* __restrict__ out4 = (float4*)out;
    const size_t rowbase =
        ((size_t)b * (HH * HH) + (size_t)y * HH + w0) * (size_t)(NB * C / 4)
        + (size_t)cg * (CSUB / 4);

    for (int tch = wid; tch < WT * NB; tch += THREADS / 32) {
        int wl = tch / NB;                 // magic-mul div
        int n  = tch - wl * NB;
        int di = n / 3;
        int pos = 18 * di + n + wl;        // = di*LW + (wl + dj)

        float4 v = *(const float4*)&sm[pos * CP + lane * 4];
        out4[rowbase + (size_t)wl * (NB * C / 4) + n * (C / 4) + lane] = v;
    }
}

extern "C" void kernel_launch(void* const* d_in, const int* in_sizes, int n_in,
                              void* d_out, int out_size) {
    const float* fm = (const float*)d_in[0];
    float* out = (float*)d_out;
    (void)in_sizes; (void)n_in; (void)out_size;

    dim3 grid(2 * NCG, HH, 16);   // (8, 38, 16) = 4864 CTAs
    spatialpool_kernel<<<grid, THREADS>>>(fm, out);
}